// round 7
// baseline (speedup 1.0000x reference)
#include <cuda_runtime.h>
#include <math.h>
typedef unsigned long long ull;

#define TSTEPS 512
#define HDIM 1024

#define FFMA2(acc,a,b) asm("fma.rn.f32x2 %0, %1, %2, %0;" : "+l"(acc) : "l"(a), "l"(b))
__device__ __forceinline__ float psum(ull v){
    float x, y;
    asm("mov.b64 {%0,%1}, %2;" : "=f"(x), "=f"(y) : "l"(v));
    return x + y;
}

__device__ int g_cnt[4 * TSTEPS];
__global__ void reset_kernel(){
    int i = blockIdx.x * blockDim.x + threadIdx.x;
    if (i < 4 * TSTEPS) g_cnt[i] = 0;
}

// ---------------------------------------------------------------------------
// Phase 1: C[65536,1024] = A @ W + b.
// CTA tile 128x128, 256 threads, 8x8 per thread (strided 16), BK=16,
// double-buffered, K-paired FFMA2 accumulators.
// sA row-major stride 20. sB k-pair interleaved: [kp][2n+par].
// ---------------------------------------------------------------------------
#define SA 20
__global__ void __launch_bounds__(256, 1) gemm_xw(
    const float* __restrict__ A, const float* __restrict__ W,
    const float* __restrict__ bias, float* __restrict__ C)
{
    __shared__ float sA[2][128 * SA];
    __shared__ float sB[2][8 * 256];
    const int tid = threadIdx.x;
    const int n0 = blockIdx.x * 128, m0 = blockIdx.y * 128;
    const int ty = tid >> 4, tx = tid & 15;       // rows ty+16i, cols tx+16j
    const int ar = tid >> 1, ah = (tid & 1) * 8;  // A staging
    const int wn = tid & 127, wk0 = tid >> 7;     // W staging

    ull acc[8][8];
    #pragma unroll
    for (int i = 0; i < 8; i++)
        #pragma unroll
        for (int j = 0; j < 8; j++) acc[i][j] = 0ull;

    const float* Ap = A + (size_t)(m0 + ar) * HDIM + ah;

    float4 pa0, pa1; float pw[8];
    pa0 = *(const float4*)Ap;
    pa1 = *(const float4*)(Ap + 4);
    #pragma unroll
    for (int q = 0; q < 4; q++) {
        int kp = wk0 + q * 2;
        pw[q*2+0] = W[(size_t)(2*kp+0) * HDIM + n0 + wn];
        pw[q*2+1] = W[(size_t)(2*kp+1) * HDIM + n0 + wn];
    }
    int buf = 0;
    *(float4*)&sA[0][ar*SA + ah] = pa0;
    *(float4*)&sA[0][ar*SA + ah + 4] = pa1;
    #pragma unroll
    for (int q = 0; q < 4; q++) {
        int kp = wk0 + q * 2;
        sB[0][kp*256 + 2*wn]     = pw[q*2+0];
        sB[0][kp*256 + 2*wn + 1] = pw[q*2+1];
    }
    __syncthreads();

    for (int kt = 0; kt < HDIM / 16; kt++) {
        if (kt < HDIM/16 - 1) {
            const float* An = Ap + (kt + 1) * 16;
            pa0 = *(const float4*)An;
            pa1 = *(const float4*)(An + 4);
            #pragma unroll
            for (int q = 0; q < 4; q++) {
                int kp = wk0 + q * 2;
                int k = (kt + 1) * 16 + 2 * kp;
                pw[q*2+0] = W[(size_t)k * HDIM + n0 + wn];
                pw[q*2+1] = W[(size_t)(k+1) * HDIM + n0 + wn];
            }
        }
        const float* cA = sA[buf];
        const float* cB = sB[buf];
        #pragma unroll
        for (int kq = 0; kq < 4; kq++) {
            ull a0[8], a1[8], w0[8], w1[8];
            #pragma unroll
            for (int i = 0; i < 8; i++) {
                ulonglong2 v = *(const ulonglong2*)&cA[(ty + 16*i) * SA + kq*4];
                a0[i] = v.x; a1[i] = v.y;
            }
            #pragma unroll
            for (int j = 0; j < 8; j++) {
                w0[j] = *(const ull*)&cB[(kq*2+0)*256 + 2*(tx + 16*j)];
                w1[j] = *(const ull*)&cB[(kq*2+1)*256 + 2*(tx + 16*j)];
            }
            #pragma unroll
            for (int i = 0; i < 8; i++)
                #pragma unroll
                for (int j = 0; j < 8; j++) {
                    FFMA2(acc[i][j], a0[i], w0[j]);
                    FFMA2(acc[i][j], a1[i], w1[j]);
                }
        }
        if (kt < HDIM/16 - 1) {
            int nb = buf ^ 1;
            *(float4*)&sA[nb][ar*SA + ah] = pa0;
            *(float4*)&sA[nb][ar*SA + ah + 4] = pa1;
            #pragma unroll
            for (int q = 0; q < 4; q++) {
                int kp = wk0 + q * 2;
                sB[nb][kp*256 + 2*wn]     = pw[q*2+0];
                sB[nb][kp*256 + 2*wn + 1] = pw[q*2+1];
            }
        }
        __syncthreads();
        buf ^= 1;
    }
    #pragma unroll
    for (int j = 0; j < 8; j++) {
        float bb = bias[n0 + tx + 16*j];
        #pragma unroll
        for (int i = 0; i < 8; i++)
            C[(size_t)(m0 + ty + 16*i) * HDIM + n0 + tx + 16*j] = psum(acc[i][j]) + bb;
    }
}

// ---------------------------------------------------------------------------
// Phase 2: persistent scan. Grid (32 cg, 4 rg) = 128 CTAs, 64 threads.
// CTA owns 32x32 tile all 512 steps. WhT slice (k-pair interleaved, 128KB)
// resident in smem. h chunk (32x128, row-major) double-buffered per step.
// Thread tile 4 rows x 4 cols, K-paired FFMA2.
// ---------------------------------------------------------------------------
#define SHS 130
#define SCAN_SMEM ((512*64 + 2*32*SHS) * 4)
__global__ void __launch_bounds__(64, 1) scan_kernel(
    const float* __restrict__ h0, const float* __restrict__ Wh,
    float* __restrict__ out)
{
    extern __shared__ float sm[];
    float* sWt = sm;               // [512 kp][64] : (Wh[2kp][n],Wh[2kp+1][n]) at kp*64+2n
    float* sh  = sm + 512 * 64;    // [2][32][SHS] row-major h chunk

    const int tid = threadIdx.x;
    const int cg = blockIdx.x, rg = blockIdx.y;
    const int ty = tid >> 3, tx = tid & 7;   // rows ty*4+i, cols tx+8*j
    const int c0 = cg * 32;

    for (int idx = tid; idx < 512 * 32; idx += 64) {
        int kp = idx >> 5, n = idx & 31;
        sWt[kp*64 + 2*n]     = Wh[(size_t)(2*kp)   * HDIM + c0 + n];
        sWt[kp*64 + 2*n + 1] = Wh[(size_t)(2*kp+1) * HDIM + c0 + n];
    }
    __syncthreads();

    const int rs = tid >> 1, rhalf = (tid & 1) * 64;
    const int grow = rg * 32 + rs;
    int* cnt = &g_cnt[rg * TSTEPS];

    for (int t = 0; t < TSTEPS; t++) {
        const float* hrow = (t == 0)
            ? h0 + (size_t)grow * HDIM
            : out + ((size_t)grow * TSTEPS + (t - 1)) * HDIM;

        ull acc[4][4];
        #pragma unroll
        for (int i = 0; i < 4; i++)
            #pragma unroll
            for (int j = 0; j < 4; j++) acc[i][j] = 0ull;

        float4 pf[16];
        #pragma unroll
        for (int q = 0; q < 16; q++)
            pf[q] = *(const float4*)&hrow[rhalf + q * 4];

        int buf = 0;
        for (int c = 0; c < 8; c++) {
            float* dst = sh + buf * 32 * SHS + rs * SHS + rhalf;
            #pragma unroll
            for (int q = 0; q < 16; q++) {
                *(float2*)&dst[q*4]     = make_float2(pf[q].x, pf[q].y);
                *(float2*)&dst[q*4 + 2] = make_float2(pf[q].z, pf[q].w);
            }
            __syncthreads();
            if (c < 7) {
                const float* src = &hrow[(c + 1) * 128 + rhalf];
                #pragma unroll
                for (int q = 0; q < 16; q++)
                    pf[q] = *(const float4*)&src[q * 4];
            }
            const float* ch = sh + buf * 32 * SHS;
            const float* cw = sWt + (size_t)c * 64 * 64;
            #pragma unroll 8
            for (int lk = 0; lk < 64; lk++) {
                ull a2[4], w2[4];
                #pragma unroll
                for (int i = 0; i < 4; i++)
                    a2[i] = *(const ull*)&ch[(ty*4 + i) * SHS + 2*lk];
                #pragma unroll
                for (int j = 0; j < 4; j++)
                    w2[j] = *(const ull*)&cw[lk*64 + 2*(tx + 8*j)];
                #pragma unroll
                for (int i = 0; i < 4; i++)
                    #pragma unroll
                    for (int j = 0; j < 4; j++)
                        FFMA2(acc[i][j], a2[i], w2[j]);
            }
            buf ^= 1;
        }

        #pragma unroll
        for (int i = 0; i < 4; i++) {
            int m = rg * 32 + ty * 4 + i;
            float* po = out + ((size_t)m * TSTEPS + t) * HDIM + c0;
            #pragma unroll
            for (int j = 0; j < 4; j++) {
                int n = tx + 8 * j;
                po[n] = tanhf(psum(acc[i][j]) + po[n]);
            }
        }

        if (t < TSTEPS - 1) {
            __threadfence();
            __syncthreads();
            if (tid == 0) {
                atomicAdd(cnt + t, 1);
                while (((volatile int*)cnt)[t] < 32) { }
                __threadfence();
            }
            __syncthreads();
        }
    }
}

extern "C" void kernel_launch(void* const* d_in, const int* in_sizes, int n_in,
                              void* d_out, int out_size) {
    const float* x  = (const float*)d_in[0];
    const float* h0 = (const float*)d_in[1];
    const float* Wx = (const float*)d_in[2];
    const float* Wh = (const float*)d_in[3];
    const float* b  = (const float*)d_in[4];
    float* out = (float*)d_out;

    {
        dim3 grid(HDIM / 128, 65536 / 128);
        gemm_xw<<<grid, 256>>>(x, Wx, b, out);
    }
    reset_kernel<<<4, 512>>>();
    {
        static int done = 0;
        if (!done) {
            cudaFuncSetAttribute(scan_kernel,
                cudaFuncAttributeMaxDynamicSharedMemorySize, SCAN_SMEM);
            done = 1;
        }
        dim3 grid(32, 4);
        scan_kernel<<<grid, 64, SCAN_SMEM>>>(h0, Wh, out);
    }
}